// round 1
// baseline (speedup 1.0000x reference)
#include <cuda_runtime.h>
#include <math.h>

#define Bn   32
#define Tn   512
#define Mn   2048
#define Ln   1024
#define NMEL 80
#define DSPK 256

#define MEL_BLOCKS  1024
#define ATTN_CHUNKS 32          // t-chunks per batch (512/16)
#define ATTN_BLOCKS (Bn * ATTN_CHUNKS)   // 1024
#define DUR_BLOCKS  64
#define NTHREADS    256

// ---- scratch (partials; each block writes its own slot -> deterministic) ----
__device__ float g_mel_partial[MEL_BLOCKS];
__device__ float g_post_partial[MEL_BLOCKS];
__device__ float g_attn_num[ATTN_BLOCKS];
__device__ float g_attn_den[ATTN_BLOCKS];
__device__ float g_dur_partial[DUR_BLOCKS];

__device__ __forceinline__ float block_reduce(float v, float* sh) {
    int tid = threadIdx.x;
    #pragma unroll
    for (int o = 16; o > 0; o >>= 1) v += __shfl_down_sync(0xffffffffu, v, o);
    if ((tid & 31) == 0) sh[tid >> 5] = v;
    __syncthreads();
    float r = 0.0f;
    if (tid < 8) {
        r = sh[tid];
        #pragma unroll
        for (int o = 4; o > 0; o >>= 1) r += __shfl_down_sync(0xffu, r, o);
    }
    __syncthreads();   // shared array reusable after return
    return r;          // valid on tid 0
}

__global__ __launch_bounds__(NTHREADS)
void partials_kernel(const float* __restrict__ mel_t,
                     const float* __restrict__ mel_p,
                     const float* __restrict__ post_p,
                     const int*   __restrict__ mel_lens,
                     const float* __restrict__ attn,
                     const int*   __restrict__ x_len,
                     const int*   __restrict__ lip_len,
                     const float* __restrict__ logdur_p,
                     const int*   __restrict__ dur_t)
{
    __shared__ float sh[8];
    const int bid = blockIdx.x;
    const int tid = threadIdx.x;

    if (bid < MEL_BLOCKS) {
        // ---- masked |pred-tgt| sums over [B, M, 80], float4 granularity ----
        __shared__ int s_len[Bn];
        if (tid < Bn) s_len[tid] = mel_lens[tid];
        __syncthreads();
        const int F = Bn * Mn * (NMEL / 4);        // 1,310,720 float4s
        float s1 = 0.0f, s2 = 0.0f;
        for (int f = bid * NTHREADS + tid; f < F; f += MEL_BLOCKS * NTHREADS) {
            int b = f / (Mn * (NMEL / 4));
            int m = (f / (NMEL / 4)) % Mn;
            if (m < s_len[b]) {
                float4 t4 = reinterpret_cast<const float4*>(mel_t)[f];
                float4 p4 = reinterpret_cast<const float4*>(mel_p)[f];
                float4 q4 = reinterpret_cast<const float4*>(post_p)[f];
                s1 += fabsf(p4.x - t4.x) + fabsf(p4.y - t4.y)
                    + fabsf(p4.z - t4.z) + fabsf(p4.w - t4.w);
                s2 += fabsf(q4.x - t4.x) + fabsf(q4.y - t4.y)
                    + fabsf(q4.z - t4.z) + fabsf(q4.w - t4.w);
            }
        }
        float r1 = block_reduce(s1, sh);
        float r2 = block_reduce(s2, sh);
        if (tid == 0) { g_mel_partial[bid] = r1; g_post_partial[bid] = r2; }
    } else if (bid < MEL_BLOCKS + ATTN_BLOCKS) {
        // ---- attention diagonal-focus partial sums ----
        const int id = bid - MEL_BLOCKS;
        const int b  = id / ATTN_CHUNKS;
        const int c  = id % ATTN_CHUNKS;
        const int xl = x_len[b];
        const int ll = lip_len[b];
        const float ks = (float)ll / (float)xl;
        const float da = (float)ll * 0.125f;       // lip_len / DIAR(8)
        float num = 0.0f, den = 0.0f;
        const int l0 = tid * 4;
        const int t_beg = c * (Tn / ATTN_CHUNKS);
        const int t_end = t_beg + (Tn / ATTN_CHUNKS);
        for (int t = t_beg; t < t_end; ++t) {
            if (t >= xl) continue;                 // src mask zeroes these rows
            const float kt = __fmul_rn(ks, (float)t);
            const float y1 = floorf(__fadd_rn(kt, da));
            const float y2 = floorf(fmaxf(__fsub_rn(kt, da), 0.0f));
            float4 v = reinterpret_cast<const float4*>(
                           attn + ((size_t)b * Tn + t) * Ln)[tid];
            #pragma unroll
            for (int j = 0; j < 4; ++j) {
                const float vv = (&v.x)[j];
                const int   l  = l0 + j;
                if (l < ll) {                      // lip mask
                    den += vv;
                    const float lf = (float)l;
                    if (lf >= y2 && lf < y1) num += vv;
                }
            }
        }
        float rn = block_reduce(num, sh);
        float rd = block_reduce(den, sh);
        if (tid == 0) { g_attn_num[id] = rn; g_attn_den[id] = rd; }
    } else {
        // ---- duration MSE in log domain ----
        const int id  = bid - MEL_BLOCKS - ATTN_BLOCKS;   // 0..63
        const int idx = id * NTHREADS + tid;              // < 16384 = B*T
        const int b = idx / Tn;
        const int t = idx % Tn;
        float s = 0.0f;
        if (t < x_len[b]) {
            float d = logdur_p[idx] - logf((float)dur_t[idx] + 1.0f);
            s = d * d;
        }
        float r = block_reduce(s, sh);
        if (tid == 0) g_dur_partial[id] = r;
    }
}

__global__ __launch_bounds__(NTHREADS)
void final_kernel(const float* __restrict__ spk_p,
                  const float* __restrict__ spk_e,
                  const int*   __restrict__ mel_lens,
                  const int*   __restrict__ x_len,
                  float* __restrict__ out)
{
    __shared__ float sh[8];
    __shared__ float res[8];   // 0:s_mel 1:s_post 2:dur 3:focus_sum 4:spk_sum
    const int tid = threadIdx.x;

    // mel / postnet sums
    float s1 = 0.0f, s2 = 0.0f;
    for (int i = tid; i < MEL_BLOCKS; i += NTHREADS) {
        s1 += g_mel_partial[i];
        s2 += g_post_partial[i];
    }
    float r = block_reduce(s1, sh); if (tid == 0) res[0] = r;
    r = block_reduce(s2, sh);       if (tid == 0) res[1] = r;

    // duration sum
    float sd = 0.0f;
    for (int i = tid; i < DUR_BLOCKS; i += NTHREADS) sd += g_dur_partial[i];
    r = block_reduce(sd, sh);       if (tid == 0) res[2] = r;

    // per-batch attention focus -> mean (warp 0, lane = batch)
    if (tid < 32) {
        float n = 0.0f, d = 0.0f;
        for (int c = 0; c < ATTN_CHUNKS; ++c) {
            n += g_attn_num[tid * ATTN_CHUNKS + c];
            d += g_attn_den[tid * ATTN_CHUNKS + c];
        }
        float focus = n / d;
        #pragma unroll
        for (int o = 16; o > 0; o >>= 1) focus += __shfl_down_sync(0xffffffffu, focus, o);
        if (tid == 0) res[3] = focus;
    }

    // speaker cosine: 8 warps x 4 batches
    {
        const int w = tid >> 5, lane = tid & 31;
        float acc = 0.0f;
        for (int i = 0; i < 4; ++i) {
            const int b = w * 4 + i;
            float dot = 0.0f, n1 = 0.0f, n2 = 0.0f;
            #pragma unroll
            for (int e = 0; e < DSPK / 32; ++e) {
                float p = spk_p[b * DSPK + lane + e * 32];
                float q = spk_e[b * DSPK + lane + e * 32];
                dot += p * q; n1 += p * p; n2 += q * q;
            }
            #pragma unroll
            for (int o = 16; o > 0; o >>= 1) {
                dot += __shfl_down_sync(0xffffffffu, dot, o);
                n1  += __shfl_down_sync(0xffffffffu, n1, o);
                n2  += __shfl_down_sync(0xffffffffu, n2, o);
            }
            if (lane == 0) {
                const float eps = 1e-6f;
                float cosv = dot / (fmaxf(sqrtf(n1), eps) * fmaxf(sqrtf(n2), eps));
                acc += 1.0f - cosv;
            }
        }
        if (lane == 0) sh[w] = acc;
    }
    __syncthreads();

    if (tid == 0) {
        float spk_sum = 0.0f;
        #pragma unroll
        for (int w = 0; w < 8; ++w) spk_sum += sh[w];

        float cnt_rows = 0.0f, xsum = 0.0f;
        for (int b = 0; b < Bn; ++b) {
            cnt_rows += (float)mel_lens[b];
            xsum     += (float)x_len[b];
        }
        const float cnt = cnt_rows * (float)NMEL;

        const float mel_loss      = res[0] / cnt;               // MEL_LW = 1
        const float postnet_loss  = res[1] / cnt;
        const float duration_loss = res[2] / xsum;               // DUR_W = 1
        const float speaker_loss  = spk_sum / (float)Bn;         // SPK_W = 1
        const float diagonal_loss = 0.1f * -logf(res[3] / (float)Bn);  // DIA_LW = 0.1
        const float total = mel_loss + postnet_loss + duration_loss
                          + speaker_loss + diagonal_loss;
        out[0] = total;
        out[1] = mel_loss;
        out[2] = postnet_loss;
        out[3] = speaker_loss;
        out[4] = duration_loss;
        out[5] = diagonal_loss;
    }
}

extern "C" void kernel_launch(void* const* d_in, const int* in_sizes, int n_in,
                              void* d_out, int out_size)
{
    // metadata order == setup_inputs order:
    // 0 texts, 1 speaker_targets, 2 mel_targets, 3 pitch_targets, 4 energy_targets,
    // 5 mel_lens, 6 duration_targets, 7 ref_linguistic_targets, 8 mel_predictions,
    // 9 postnet_mel_predictions, 10 log_duration_predictions, 11 src_masks,
    // 12 mel_masks, 13 ref_mel_masks, 14 speaker_predicts, 15 spk_embedding,
    // 16 attn_scores, 17 x_lengths, 18 lip_length, 19 lip_masks
    const float* mel_t    = (const float*)d_in[2];
    const int*   mel_lens = (const int*)  d_in[5];
    const int*   dur_t    = (const int*)  d_in[6];
    const float* mel_p    = (const float*)d_in[8];
    const float* post_p   = (const float*)d_in[9];
    const float* logdur_p = (const float*)d_in[10];
    const float* spk_p    = (const float*)d_in[14];
    const float* spk_e    = (const float*)d_in[15];
    const float* attn     = (const float*)d_in[16];
    const int*   x_len    = (const int*)  d_in[17];
    const int*   lip_len  = (const int*)  d_in[18];

    partials_kernel<<<MEL_BLOCKS + ATTN_BLOCKS + DUR_BLOCKS, NTHREADS>>>(
        mel_t, mel_p, post_p, mel_lens, attn, x_len, lip_len, logdur_p, dur_t);
    final_kernel<<<1, NTHREADS>>>(spk_p, spk_e, mel_lens, x_len, (float*)d_out);
}